// round 1
// baseline (speedup 1.0000x reference)
#include <cuda_runtime.h>
#include <cstdint>

// Problem shapes (fixed by setup_inputs)
#define M_DIM 256    // m (averaged out)
#define I_DIM 512    // i == j
#define D_DIM 128    // DIM
#define H_DIM 128    // HID

// Scratch (device globals; no allocation allowed)
__device__ float g_xnbar[I_DIM * D_DIM];  // mean over m of LN(x)
__device__ float g_lm[I_DIM * H_DIM];
__device__ float g_rm[I_DIM * H_DIM];
__device__ float g_L[I_DIM * D_DIM];      // left_m @ w_out
__device__ float g_R[I_DIM * D_DIM];      // right_m @ w_out + b_out

// ---------------------------------------------------------------------------
// Kernel 1: per-row LayerNorm of x[m,i,:] and mean over m -> g_xnbar[i,:]
// grid = 512 (one block per i), block = 256 (8 warps; each warp owns 32 m's)
// ---------------------------------------------------------------------------
__global__ void __launch_bounds__(256) ln_mean_kernel(
    const float* __restrict__ x,
    const float* __restrict__ ln_g,
    const float* __restrict__ ln_b)
{
    const int i = blockIdx.x;
    const int warp = threadIdx.x >> 5;
    const int lane = threadIdx.x & 31;

    // Each lane owns 4 consecutive channels: d = lane*4 + {0..3}
    const float4 gv = reinterpret_cast<const float4*>(ln_g)[lane];
    const float4 bv = reinterpret_cast<const float4*>(ln_b)[lane];

    float a0 = 0.f, a1 = 0.f, a2 = 0.f, a3 = 0.f;

    #pragma unroll 4
    for (int m = warp; m < M_DIM; m += 8) {
        const float4 v = reinterpret_cast<const float4*>(
            x + ((size_t)m * I_DIM + i) * D_DIM)[lane];

        float s  = v.x + v.y + v.z + v.w;
        float sq = v.x*v.x + v.y*v.y + v.z*v.z + v.w*v.w;
        #pragma unroll
        for (int o = 16; o; o >>= 1) {
            s  += __shfl_xor_sync(0xffffffffu, s,  o);
            sq += __shfl_xor_sync(0xffffffffu, sq, o);
        }
        const float mu   = s * (1.f / 128.f);
        const float var  = sq * (1.f / 128.f) - mu * mu;
        const float rstd = rsqrtf(var + 1e-5f);

        a0 += (v.x - mu) * rstd * gv.x + bv.x;
        a1 += (v.y - mu) * rstd * gv.y + bv.y;
        a2 += (v.z - mu) * rstd * gv.z + bv.z;
        a3 += (v.w - mu) * rstd * gv.w + bv.w;
    }

    __shared__ float part[8][D_DIM];
    part[warp][lane * 4 + 0] = a0;
    part[warp][lane * 4 + 1] = a1;
    part[warp][lane * 4 + 2] = a2;
    part[warp][lane * 4 + 3] = a3;
    __syncthreads();

    if (threadIdx.x < D_DIM) {
        float s = 0.f;
        #pragma unroll
        for (int w = 0; w < 8; w++) s += part[w][threadIdx.x];
        g_xnbar[i * D_DIM + threadIdx.x] = s * (1.f / (float)M_DIM);
    }
}

// ---------------------------------------------------------------------------
// Kernel 2: lm = xnbar @ w_left + b_left ; rm = xnbar @ w_right + b_right
// grid = 512 (per i), block = 128 (per h)
// ---------------------------------------------------------------------------
__global__ void __launch_bounds__(128) proj_kernel(
    const float* __restrict__ wl, const float* __restrict__ bl,
    const float* __restrict__ wr, const float* __restrict__ br)
{
    const int i = blockIdx.x;
    const int h = threadIdx.x;

    __shared__ float xs[D_DIM];
    xs[h] = g_xnbar[i * D_DIM + h];
    __syncthreads();

    float al = bl[h];
    float ar = br[h];
    #pragma unroll 8
    for (int c = 0; c < D_DIM; c++) {
        const float xc = xs[c];
        al += xc * wl[c * H_DIM + h];
        ar += xc * wr[c * H_DIM + h];
    }
    g_lm[i * H_DIM + h] = al;
    g_rm[i * H_DIM + h] = ar;
}

// ---------------------------------------------------------------------------
// Kernel 3: L = lm @ w_out ; R = rm @ w_out + b_out
// grid = 512 (per i), block = 128 (per d)
// ---------------------------------------------------------------------------
__global__ void __launch_bounds__(128) outproj_kernel(
    const float* __restrict__ wo, const float* __restrict__ bo)
{
    const int i = blockIdx.x;
    const int d = threadIdx.x;

    __shared__ float ls[H_DIM], rs[H_DIM];
    ls[d] = g_lm[i * H_DIM + d];
    rs[d] = g_rm[i * H_DIM + d];
    __syncthreads();

    float aL = 0.f;
    float aR = bo[d];
    #pragma unroll 8
    for (int h = 0; h < H_DIM; h++) {
        const float w = wo[h * D_DIM + d];
        aL += ls[h] * w;
        aR += rs[h] * w;
    }
    g_L[i * D_DIM + d] = aL;
    g_R[i * D_DIM + d] = aR;
}

// ---------------------------------------------------------------------------
// Kernel 4: out[i,j,:] = L[i,:] + R[j,:]   (134 MB of stores; BW-bound)
// grid = (512, 16), block = 256. Each block: one i, 32 j's. float4 I/O.
// ---------------------------------------------------------------------------
__global__ void __launch_bounds__(256) broadcast_kernel(float* __restrict__ out)
{
    const int i  = blockIdx.x;
    const int j0 = blockIdx.y * 32;
    const int d4 = threadIdx.x & 31;   // float4 index within row (32 * 4 = 128)
    const int jl = threadIdx.x >> 5;   // 8 local j's per pass

    const float4 Lv = reinterpret_cast<const float4*>(g_L)[i * 32 + d4];
    const float4* __restrict__ R4 = reinterpret_cast<const float4*>(g_R);
    float4* __restrict__ o4 = reinterpret_cast<float4*>(out);

    #pragma unroll
    for (int p = 0; p < 4; p++) {
        const int j = j0 + jl + p * 8;
        const float4 Rv = R4[j * 32 + d4];
        float4 o;
        o.x = Lv.x + Rv.x;
        o.y = Lv.y + Rv.y;
        o.z = Lv.z + Rv.z;
        o.w = Lv.w + Rv.w;
        o4[((size_t)i * I_DIM + j) * 32 + d4] = o;
    }
}

// ---------------------------------------------------------------------------
extern "C" void kernel_launch(void* const* d_in, const int* in_sizes, int n_in,
                              void* d_out, int out_size)
{
    const float* x    = (const float*)d_in[0];
    const float* ln_g = (const float*)d_in[1];
    const float* ln_b = (const float*)d_in[2];
    const float* wl   = (const float*)d_in[3];
    const float* bl   = (const float*)d_in[4];
    const float* wr   = (const float*)d_in[5];
    const float* br   = (const float*)d_in[6];
    const float* wo   = (const float*)d_in[7];
    const float* bo   = (const float*)d_in[8];
    float* out = (float*)d_out;

    ln_mean_kernel<<<I_DIM, 256>>>(x, ln_g, ln_b);
    proj_kernel<<<I_DIM, 128>>>(wl, bl, wr, br);
    outproj_kernel<<<I_DIM, 128>>>(wo, bo);
    broadcast_kernel<<<dim3(I_DIM, 16), 256>>>(out);
}

// round 2
// speedup vs baseline: 1.0542x; 1.0542x over previous
#include <cuda_runtime.h>
#include <cstdint>

// Problem shapes (fixed by setup_inputs)
#define M_DIM 256    // m (averaged out)
#define I_DIM 512    // i == j
#define D_DIM 128    // DIM
#define H_DIM 128    // HID

// Scratch (device globals; no allocation allowed)
__device__ float g_xnbar[I_DIM * D_DIM];  // mean over m of LN(x)
__device__ float g_L[I_DIM * D_DIM];      // left_m @ w_out
__device__ float g_R[I_DIM * D_DIM];      // right_m @ w_out + b_out

// ---------------------------------------------------------------------------
// Kernel 1: per-row LayerNorm of x[m,i,:] and mean over m -> g_xnbar[i,:]
// grid = 512 (one block per i), block = 256 (8 warps; each warp owns 32 m's)
// m-loop unrolled x4: 4 independent loads in flight, 4 interleaved shuffle
// trees -> latency hidden, kernel becomes DRAM-bound.
// ---------------------------------------------------------------------------
__global__ void __launch_bounds__(256) ln_mean_kernel(
    const float* __restrict__ x,
    const float* __restrict__ ln_g,
    const float* __restrict__ ln_b)
{
    const int i = blockIdx.x;
    const int warp = threadIdx.x >> 5;
    const int lane = threadIdx.x & 31;

    // Each lane owns 4 consecutive channels: d = lane*4 + {0..3}
    const float4 gv = reinterpret_cast<const float4*>(ln_g)[lane];
    const float4 bv = reinterpret_cast<const float4*>(ln_b)[lane];

    float a0 = 0.f, a1 = 0.f, a2 = 0.f, a3 = 0.f;

    // base pointer for this warp's first m and this i
    const float4* __restrict__ x4 = reinterpret_cast<const float4*>(x);

    #pragma unroll 1
    for (int t = 0; t < 32; t += 4) {
        float4 v[4];
        #pragma unroll
        for (int u = 0; u < 4; u++) {
            const int m = warp + (t + u) * 8;
            v[u] = x4[((size_t)m * I_DIM + i) * 32 + lane];
        }

        float s[4], sq[4];
        #pragma unroll
        for (int u = 0; u < 4; u++) {
            s[u]  = v[u].x + v[u].y + v[u].z + v[u].w;
            sq[u] = v[u].x*v[u].x + v[u].y*v[u].y + v[u].z*v[u].z + v[u].w*v[u].w;
        }
        // 4 independent butterfly reductions, interleaved
        #pragma unroll
        for (int o = 16; o; o >>= 1) {
            #pragma unroll
            for (int u = 0; u < 4; u++) {
                s[u]  += __shfl_xor_sync(0xffffffffu, s[u],  o);
                sq[u] += __shfl_xor_sync(0xffffffffu, sq[u], o);
            }
        }
        #pragma unroll
        for (int u = 0; u < 4; u++) {
            const float mu   = s[u] * (1.f / 128.f);
            const float var  = sq[u] * (1.f / 128.f) - mu * mu;
            const float rstd = rsqrtf(var + 1e-5f);
            a0 += (v[u].x - mu) * rstd;
            a1 += (v[u].y - mu) * rstd;
            a2 += (v[u].z - mu) * rstd;
            a3 += (v[u].w - mu) * rstd;
        }
    }

    // apply gamma/beta once at the end:
    // sum_m [ (v-mu)*rstd*g + b ] = g * sum_m[(v-mu)*rstd] + M*b
    a0 = a0 * gv.x + (float)M_DIM * bv.x;
    a1 = a1 * gv.y + (float)M_DIM * bv.y;
    a2 = a2 * gv.z + (float)M_DIM * bv.z;
    a3 = a3 * gv.w + (float)M_DIM * bv.w;

    __shared__ float part[8][D_DIM];
    part[warp][lane * 4 + 0] = a0;
    part[warp][lane * 4 + 1] = a1;
    part[warp][lane * 4 + 2] = a2;
    part[warp][lane * 4 + 3] = a3;
    __syncthreads();

    if (threadIdx.x < D_DIM) {
        float sum = 0.f;
        #pragma unroll
        for (int w = 0; w < 8; w++) sum += part[w][threadIdx.x];
        g_xnbar[i * D_DIM + threadIdx.x] = sum * (1.f / (float)M_DIM);
    }
}

// ---------------------------------------------------------------------------
// Kernel 2 (fused): lm = xnbar@wl + bl ; rm = xnbar@wr + br ;
//                   L = lm@wo ; R = rm@wo + bo
// grid = 512 (per i), block = 128
// ---------------------------------------------------------------------------
__global__ void __launch_bounds__(128) proj_fused_kernel(
    const float* __restrict__ wl, const float* __restrict__ bl,
    const float* __restrict__ wr, const float* __restrict__ br,
    const float* __restrict__ wo, const float* __restrict__ bo)
{
    const int i = blockIdx.x;
    const int h = threadIdx.x;

    __shared__ float xs[D_DIM];
    __shared__ float ls[H_DIM], rs[H_DIM];

    xs[h] = g_xnbar[i * D_DIM + h];
    __syncthreads();

    float al = bl[h];
    float ar = br[h];
    #pragma unroll 8
    for (int c = 0; c < D_DIM; c++) {
        const float xc = xs[c];
        al += xc * wl[c * H_DIM + h];
        ar += xc * wr[c * H_DIM + h];
    }
    ls[h] = al;
    rs[h] = ar;
    __syncthreads();

    float aL = 0.f;
    float aR = bo[h];
    #pragma unroll 8
    for (int c = 0; c < H_DIM; c++) {
        const float w = wo[c * D_DIM + h];
        aL += ls[c] * w;
        aR += rs[c] * w;
    }
    g_L[i * D_DIM + h] = aL;
    g_R[i * D_DIM + h] = aR;
}

// ---------------------------------------------------------------------------
// Kernel 3: out[i,j,:] = L[i,:] + R[j,:]   (134 MB of stores; BW-bound)
// grid = (512, 16), block = 256. Streaming stores (__stcs): output is
// write-once, never re-read -> don't pollute L2.
// ---------------------------------------------------------------------------
__global__ void __launch_bounds__(256) broadcast_kernel(float* __restrict__ out)
{
    const int i  = blockIdx.x;
    const int j0 = blockIdx.y * 32;
    const int d4 = threadIdx.x & 31;   // float4 index within row (32 * 4 = 128)
    const int jl = threadIdx.x >> 5;   // 8 local j's per pass

    const float4 Lv = reinterpret_cast<const float4*>(g_L)[i * 32 + d4];
    const float4* __restrict__ R4 = reinterpret_cast<const float4*>(g_R);
    float4* __restrict__ o4 = reinterpret_cast<float4*>(out);

    #pragma unroll
    for (int p = 0; p < 4; p++) {
        const int j = j0 + jl + p * 8;
        const float4 Rv = __ldg(&R4[j * 32 + d4]);
        float4 o;
        o.x = Lv.x + Rv.x;
        o.y = Lv.y + Rv.y;
        o.z = Lv.z + Rv.z;
        o.w = Lv.w + Rv.w;
        __stcs(&o4[((size_t)i * I_DIM + j) * 32 + d4], o);
    }
}

// ---------------------------------------------------------------------------
extern "C" void kernel_launch(void* const* d_in, const int* in_sizes, int n_in,
                              void* d_out, int out_size)
{
    const float* x    = (const float*)d_in[0];
    const float* ln_g = (const float*)d_in[1];
    const float* ln_b = (const float*)d_in[2];
    const float* wl   = (const float*)d_in[3];
    const float* bl   = (const float*)d_in[4];
    const float* wr   = (const float*)d_in[5];
    const float* br   = (const float*)d_in[6];
    const float* wo   = (const float*)d_in[7];
    const float* bo   = (const float*)d_in[8];
    float* out = (float*)d_out;

    ln_mean_kernel<<<I_DIM, 256>>>(x, ln_g, ln_b);
    proj_fused_kernel<<<I_DIM, 128>>>(wl, bl, wr, br, wo, bo);
    broadcast_kernel<<<dim3(I_DIM, 16), 256>>>(out);
}

// round 6
// speedup vs baseline: 1.1297x; 1.0716x over previous
#include <cuda_runtime.h>
#include <cstdint>

#define M_DIM 256
#define I_DIM 512
#define D_DIM 128
#define H_DIM 128
#define MSPLIT 4
#define M_PER  (M_DIM / MSPLIT)   // 64 m's per block

// Scratch (device globals; no allocation allowed)
__device__ float g_part[MSPLIT * I_DIM * D_DIM]; // raw sums of (v-mu)*rstd
__device__ float g_L[I_DIM * D_DIM];
__device__ float g_R[I_DIM * D_DIM];

// ---------------------------------------------------------------------------
// Kernel 1: partial LayerNorm-sum. grid=(512, MSPLIT), block=256.
// Block (i, z) handles m in [z*64, z*64+64); each warp owns 8 m's.
// Writes RAW sum of (v-mu)*rstd (no gamma/beta, no /M) to g_part.
// ---------------------------------------------------------------------------
__global__ void __launch_bounds__(256) ln_mean_kernel(
    const float* __restrict__ x)
{
    const int i = blockIdx.x;
    const int z = blockIdx.y;
    const int warp = threadIdx.x >> 5;
    const int lane = threadIdx.x & 31;

    float a0 = 0.f, a1 = 0.f, a2 = 0.f, a3 = 0.f;
    const float4* __restrict__ x4 = reinterpret_cast<const float4*>(x);
    const int m_base = z * M_PER + warp;

    #pragma unroll 1
    for (int t = 0; t < 8; t += 4) {
        float4 v[4];
        #pragma unroll
        for (int u = 0; u < 4; u++) {
            const int m = m_base + (t + u) * 8;
            v[u] = x4[((size_t)m * I_DIM + i) * 32 + lane];
        }
        float s[4], sq[4];
        #pragma unroll
        for (int u = 0; u < 4; u++) {
            s[u]  = v[u].x + v[u].y + v[u].z + v[u].w;
            sq[u] = v[u].x*v[u].x + v[u].y*v[u].y + v[u].z*v[u].z + v[u].w*v[u].w;
        }
        #pragma unroll
        for (int o = 16; o; o >>= 1) {
            #pragma unroll
            for (int u = 0; u < 4; u++) {
                s[u]  += __shfl_xor_sync(0xffffffffu, s[u],  o);
                sq[u] += __shfl_xor_sync(0xffffffffu, sq[u], o);
            }
        }
        #pragma unroll
        for (int u = 0; u < 4; u++) {
            const float mu   = s[u] * (1.f / 128.f);
            const float var  = sq[u] * (1.f / 128.f) - mu * mu;
            const float rstd = rsqrtf(var + 1e-5f);
            a0 += (v[u].x - mu) * rstd;
            a1 += (v[u].y - mu) * rstd;
            a2 += (v[u].z - mu) * rstd;
            a3 += (v[u].w - mu) * rstd;
        }
    }

    __shared__ float part[8][D_DIM];
    part[warp][lane * 4 + 0] = a0;
    part[warp][lane * 4 + 1] = a1;
    part[warp][lane * 4 + 2] = a2;
    part[warp][lane * 4 + 3] = a3;
    __syncthreads();

    if (threadIdx.x < D_DIM) {
        float sum = 0.f;
        #pragma unroll
        for (int w = 0; w < 8; w++) sum += part[w][threadIdx.x];
        g_part[((size_t)z * I_DIM + i) * D_DIM + threadIdx.x] = sum;
    }
}

// ---------------------------------------------------------------------------
// Kernel 2 (fused): combine partials -> xnbar; lm/rm; L/R. grid=512, block=128
// ---------------------------------------------------------------------------
__global__ void __launch_bounds__(128) proj_fused_kernel(
    const float* __restrict__ ln_g, const float* __restrict__ ln_b,
    const float* __restrict__ wl, const float* __restrict__ bl,
    const float* __restrict__ wr, const float* __restrict__ br,
    const float* __restrict__ wo, const float* __restrict__ bo)
{
    const int i = blockIdx.x;
    const int h = threadIdx.x;

    __shared__ float xs[D_DIM];
    __shared__ float ls[H_DIM], rs[H_DIM];

    float sum = 0.f;
    #pragma unroll
    for (int z = 0; z < MSPLIT; z++)
        sum += g_part[((size_t)z * I_DIM + i) * D_DIM + h];
    xs[h] = sum * (1.f / (float)M_DIM) * ln_g[h] + ln_b[h];
    __syncthreads();

    float al = bl[h];
    float ar = br[h];
    #pragma unroll 8
    for (int c = 0; c < D_DIM; c++) {
        const float xc = xs[c];
        al += xc * wl[c * H_DIM + h];
        ar += xc * wr[c * H_DIM + h];
    }
    ls[h] = al;
    rs[h] = ar;
    __syncthreads();

    float aL = 0.f;
    float aR = bo[h];
    #pragma unroll 8
    for (int c = 0; c < H_DIM; c++) {
        const float w = wo[c * D_DIM + h];
        aL += ls[c] * w;
        aR += rs[c] * w;
    }
    g_L[i * D_DIM + h] = aL;
    g_R[i * D_DIM + h] = aR;
}

// ---------------------------------------------------------------------------
// Kernel 3: out[i,j,:] = L[i,:] + R[j,:]  (134 MB stores; streaming)
// ---------------------------------------------------------------------------
__global__ void __launch_bounds__(256) broadcast_kernel(float* __restrict__ out)
{
    const int i  = blockIdx.x;
    const int j0 = blockIdx.y * 32;
    const int d4 = threadIdx.x & 31;
    const int jl = threadIdx.x >> 5;

    const float4 Lv = reinterpret_cast<const float4*>(g_L)[i * 32 + d4];
    const float4* __restrict__ R4 = reinterpret_cast<const float4*>(g_R);
    float4* __restrict__ o4 = reinterpret_cast<float4*>(out);

    #pragma unroll
    for (int p = 0; p < 4; p++) {
        const int j = j0 + jl + p * 8;
        const float4 Rv = __ldg(&R4[j * 32 + d4]);
        float4 o;
        o.x = Lv.x + Rv.x;
        o.y = Lv.y + Rv.y;
        o.z = Lv.z + Rv.z;
        o.w = Lv.w + Rv.w;
        __stcs(&o4[((size_t)i * I_DIM + j) * 32 + d4], o);
    }
}

// ---------------------------------------------------------------------------
extern "C" void kernel_launch(void* const* d_in, const int* in_sizes, int n_in,
                              void* d_out, int out_size)
{
    const float* x    = (const float*)d_in[0];
    const float* ln_g = (const float*)d_in[1];
    const float* ln_b = (const float*)d_in[2];
    const float* wl   = (const float*)d_in[3];
    const float* bl   = (const float*)d_in[4];
    const float* wr   = (const float*)d_in[5];
    const float* br   = (const float*)d_in[6];
    const float* wo   = (const float*)d_in[7];
    const float* bo   = (const float*)d_in[8];
    float* out = (float*)d_out;

    ln_mean_kernel<<<dim3(I_DIM, MSPLIT), 256>>>(x);
    proj_fused_kernel<<<I_DIM, 128>>>(ln_g, ln_b, wl, bl, wr, br, wo, bo);
    broadcast_kernel<<<dim3(I_DIM, 16), 256>>>(out);
}

// round 7
// speedup vs baseline: 1.1616x; 1.0283x over previous
#include <cuda_runtime.h>
#include <cstdint>

#define M_DIM 256
#define I_DIM 512
#define D_DIM 128
#define H_DIM 128
#define MSPLIT 4
#define M_PER  (M_DIM / MSPLIT)   // 64 m's per block

// Scratch (device globals; no allocation allowed)
__device__ float g_part[MSPLIT * I_DIM * D_DIM]; // raw sums of (v-mu)*rstd
__device__ float g_L[I_DIM * D_DIM];
__device__ float g_R[I_DIM * D_DIM];
__device__ int   g_cnt[I_DIM];                   // zero-init; self-resetting

// ---------------------------------------------------------------------------
// Kernel 1 (fused): partial LayerNorm-sum + (last block per i) proj chain.
// grid=(512, MSPLIT), block=256.
// ---------------------------------------------------------------------------
__global__ void __launch_bounds__(256) ln_proj_kernel(
    const float* __restrict__ x,
    const float* __restrict__ ln_g, const float* __restrict__ ln_b,
    const float* __restrict__ wl, const float* __restrict__ bl,
    const float* __restrict__ wr, const float* __restrict__ br,
    const float* __restrict__ wo, const float* __restrict__ bo)
{
    const int i = blockIdx.x;
    const int z = blockIdx.y;
    const int warp = threadIdx.x >> 5;
    const int lane = threadIdx.x & 31;

    // ---- LN partial over 64 m's ----
    float a0 = 0.f, a1 = 0.f, a2 = 0.f, a3 = 0.f;
    const float4* __restrict__ x4 = reinterpret_cast<const float4*>(x);
    const int m_base = z * M_PER + warp;

    #pragma unroll 1
    for (int t = 0; t < 8; t += 4) {
        float4 v[4];
        #pragma unroll
        for (int u = 0; u < 4; u++) {
            const int m = m_base + (t + u) * 8;
            v[u] = x4[((size_t)m * I_DIM + i) * 32 + lane];
        }
        float s[4], sq[4];
        #pragma unroll
        for (int u = 0; u < 4; u++) {
            s[u]  = v[u].x + v[u].y + v[u].z + v[u].w;
            sq[u] = v[u].x*v[u].x + v[u].y*v[u].y + v[u].z*v[u].z + v[u].w*v[u].w;
        }
        #pragma unroll
        for (int o = 16; o; o >>= 1) {
            #pragma unroll
            for (int u = 0; u < 4; u++) {
                s[u]  += __shfl_xor_sync(0xffffffffu, s[u],  o);
                sq[u] += __shfl_xor_sync(0xffffffffu, sq[u], o);
            }
        }
        #pragma unroll
        for (int u = 0; u < 4; u++) {
            const float mu   = s[u] * (1.f / 128.f);
            const float var  = sq[u] * (1.f / 128.f) - mu * mu;
            const float rstd = rsqrtf(var + 1e-5f);
            a0 += (v[u].x - mu) * rstd;
            a1 += (v[u].y - mu) * rstd;
            a2 += (v[u].z - mu) * rstd;
            a3 += (v[u].w - mu) * rstd;
        }
    }

    __shared__ float part[8][D_DIM];
    part[warp][lane * 4 + 0] = a0;
    part[warp][lane * 4 + 1] = a1;
    part[warp][lane * 4 + 2] = a2;
    part[warp][lane * 4 + 3] = a3;
    __syncthreads();

    if (threadIdx.x < D_DIM) {
        float sum = 0.f;
        #pragma unroll
        for (int w = 0; w < 8; w++) sum += part[w][threadIdx.x];
        g_part[((size_t)z * I_DIM + i) * D_DIM + threadIdx.x] = sum;
        __threadfence();   // make partial visible before arriving on counter
    }
    __syncthreads();

    // ---- arrive; last of 4 blocks for this i does the proj chain ----
    __shared__ int s_win;
    if (threadIdx.x == 0) {
        const int old = atomicAdd(&g_cnt[i], 1);
        s_win = (old == MSPLIT - 1);
        if (s_win) {
            g_cnt[i] = 0;      // self-reset for next graph replay
            __threadfence();   // acquire partials from the other 3 blocks
        }
    }
    __syncthreads();
    if (!s_win) return;

    // ---- proj for row i: 256 threads, side 0 = left, side 1 = right ----
    const int h    = threadIdx.x & 127;
    const int side = threadIdx.x >> 7;

    __shared__ float xs[D_DIM];
    __shared__ float ls[H_DIM], rs[H_DIM];

    if (threadIdx.x < D_DIM) {
        float sum = 0.f;
        #pragma unroll
        for (int zz = 0; zz < MSPLIT; zz++)
            sum += g_part[((size_t)zz * I_DIM + i) * D_DIM + threadIdx.x];
        xs[threadIdx.x] = sum * (1.f / (float)M_DIM) * ln_g[threadIdx.x]
                        + ln_b[threadIdx.x];
    }
    __syncthreads();

    {   // stage 1: lm = xs@wl + bl (side 0) / rm = xs@wr + br (side 1)
        const float* __restrict__ w1 = side ? wr : wl;
        float acc = side ? br[h] : bl[h];
        #pragma unroll 8
        for (int c = 0; c < D_DIM; c++)
            acc += xs[c] * w1[c * H_DIM + h];
        if (side) rs[h] = acc; else ls[h] = acc;
    }
    __syncthreads();

    {   // stage 2: L = ls@wo (side 0) / R = rs@wo + bo (side 1)
        const float* __restrict__ v = side ? rs : ls;
        float acc = side ? bo[h] : 0.f;
        #pragma unroll 8
        for (int c = 0; c < H_DIM; c++)
            acc += v[c] * wo[c * D_DIM + h];
        if (side) g_R[i * D_DIM + h] = acc;
        else      g_L[i * D_DIM + h] = acc;
    }
}

// ---------------------------------------------------------------------------
// Kernel 2: out[i,j,:] = L[i,:] + R[j,:]  (134 MB stores; streaming)
// ---------------------------------------------------------------------------
__global__ void __launch_bounds__(256) broadcast_kernel(float* __restrict__ out)
{
    const int i  = blockIdx.x;
    const int j0 = blockIdx.y * 32;
    const int d4 = threadIdx.x & 31;
    const int jl = threadIdx.x >> 5;

    const float4 Lv = reinterpret_cast<const float4*>(g_L)[i * 32 + d4];
    const float4* __restrict__ R4 = reinterpret_cast<const float4*>(g_R);
    float4* __restrict__ o4 = reinterpret_cast<float4*>(out);

    #pragma unroll
    for (int p = 0; p < 4; p++) {
        const int j = j0 + jl + p * 8;
        const float4 Rv = __ldg(&R4[j * 32 + d4]);
        float4 o;
        o.x = Lv.x + Rv.x;
        o.y = Lv.y + Rv.y;
        o.z = Lv.z + Rv.z;
        o.w = Lv.w + Rv.w;
        __stcs(&o4[((size_t)i * I_DIM + j) * 32 + d4], o);
    }
}

// ---------------------------------------------------------------------------
extern "C" void kernel_launch(void* const* d_in, const int* in_sizes, int n_in,
                              void* d_out, int out_size)
{
    const float* x    = (const float*)d_in[0];
    const float* ln_g = (const float*)d_in[1];
    const float* ln_b = (const float*)d_in[2];
    const float* wl   = (const float*)d_in[3];
    const float* bl   = (const float*)d_in[4];
    const float* wr   = (const float*)d_in[5];
    const float* br   = (const float*)d_in[6];
    const float* wo   = (const float*)d_in[7];
    const float* bo   = (const float*)d_in[8];
    float* out = (float*)d_out;

    ln_proj_kernel<<<dim3(I_DIM, MSPLIT), 256>>>(x, ln_g, ln_b,
                                                 wl, bl, wr, br, wo, bo);
    broadcast_kernel<<<dim3(I_DIM, 16), 256>>>(out);
}